// round 1
// baseline (speedup 1.0000x reference)
#include <cuda_runtime.h>

#define B_ 8
#define N_ 1024
#define I_ 64
#define O_ 32
#define H_ 4
#define NW 32            // adjacency words per row (N_/32)
#define TJ 128           // j-tile size in aggregation

// ---- device scratch (no allocations allowed) ----
__device__ float    g_proj[B_*H_*N_*O_];   // [b][h][j][o]  4MB
__device__ float2   g_srcsp[B_*H_*N_];     // (src_score, gain*prior)
__device__ float    g_dstsc[B_*H_*N_];     // dst score
__device__ unsigned g_adjbits[N_*NW];      // packed adjacency bits

__device__ __forceinline__ float lrelu(float v) { return v > 0.f ? v : 0.2f * v; }

__device__ __forceinline__ unsigned long long pack2(float a, float b) {
    unsigned long long r;
    asm("mov.b64 %0, {%1, %2};" : "=l"(r) : "f"(a), "f"(b));
    return r;
}
__device__ __forceinline__ void fma2(unsigned long long& d, unsigned long long a, unsigned long long b) {
    asm("fma.rn.f32x2 %0, %1, %2, %3;" : "=l"(d) : "l"(a), "l"(b), "l"(d));
}
__device__ __forceinline__ void unpack2(unsigned long long v, float& a, float& b) {
    asm("mov.b64 {%0, %1}, %2;" : "=f"(a), "=f"(b) : "l"(v));
}

// ---------------- K0: pack adjacency to bits ----------------
__global__ void k0_pack(const int* __restrict__ adj) {
    int g    = blockIdx.x * 8 + (threadIdx.x >> 5);   // global warp id
    int lane = threadIdx.x & 31;
    int i = g >> 5, w = g & 31;
    int v = adj[i * N_ + w * 32 + lane];
    unsigned bits = __ballot_sync(0xffffffffu, v != 0);
    if (lane == 0) g_adjbits[i * NW + w] = bits;
}

// ---------------- K1: projection + scores ----------------
__global__ __launch_bounds__(128) void k1_proj(
    const float* __restrict__ x, const float* __restrict__ weight,
    const float* __restrict__ bias, const float* __restrict__ attn_src,
    const float* __restrict__ attn_dst, const float* __restrict__ beta,
    const float* __restrict__ prior)
{
    __shared__ float xs[I_];
    int bn = blockIdx.x;            // = b*N_ + n
    int b = bn >> 10, n = bn & 1023;
    int tid = threadIdx.x;
    if (tid < I_) xs[tid] = x[bn * I_ + tid];
    __syncthreads();

    int h = tid >> 5, o = tid & 31;
    float acc = bias[tid];          // bias layout [H][O] == tid
    const float* wp = weight + h * I_ * O_ + o;
#pragma unroll
    for (int i = 0; i < I_; i++) acc = fmaf(xs[i], wp[i * O_], acc);

    g_proj[((b * H_ + h) * N_ + n) * O_ + o] = acc;

    float s = acc * attn_src[tid];
    float d = acc * attn_dst[tid];
#pragma unroll
    for (int off = 16; off; off >>= 1) {
        s += __shfl_xor_sync(0xffffffffu, s, off);
        d += __shfl_xor_sync(0xffffffffu, d, off);
    }
    if (o == 0) {
        int idx = (b * H_ + h) * N_ + n;
        g_dstsc[idx] = d;
        float bt = beta[h];
        float gain = (bt > 20.f) ? bt : log1pf(expf(bt));   // softplus
        g_srcsp[idx] = make_float2(s, gain * prior[b * N_ + n]);
    }
}

// ---------------- K2: fused masked softmax + aggregation ----------------
// grid: (32 dst tiles, H, B), 256 threads. warp w owns 4 dst rows.
__global__ __launch_bounds__(256) void k2_attn(float* __restrict__ out) {
    __shared__ float2 s_ss[N_];          // (src, gain*prior) per source j    8KB
    __shared__ float  s_dst[32];         // dst scores for this tile
    __shared__ float  s_P[TJ * O_];      // projected tile                    16KB
    __shared__ float4 s_e[8 * TJ];       // per-warp exp values               16KB

    int tid = threadIdx.x, lane = tid & 31, w = tid >> 5;
    int bi = blockIdx.x;                 // dst row tile
    int h  = blockIdx.y, b = blockIdx.z;
    int bh = b * H_ + h;

    const float2* gss = g_srcsp + bh * N_;
#pragma unroll
    for (int u = 0; u < 4; u++) s_ss[tid + u * 256] = gss[tid + u * 256];
    if (tid < 32) s_dst[tid] = g_dstsc[bh * N_ + bi * 32 + tid];
    __syncthreads();

    int r0 = w * 4;                      // local row base
    int i0 = bi * 32 + r0;               // global dst row base
    float dstv[4], m[4], dn[4];
#pragma unroll
    for (int q = 0; q < 4; q++) { dstv[q] = s_dst[r0 + q]; m[q] = -1e30f; dn[q] = 0.f; }

    // ---- pass 1: masked row max ----
    for (int k = 0; k < NW; k++) {
        float2 ss = s_ss[k * 32 + lane];
#pragma unroll
        for (int q = 0; q < 4; q++) {
            unsigned word = g_adjbits[(i0 + q) * NW + k];
            float lg = lrelu(dstv[q] + ss.x) + ss.y;
            float lm = ((word >> lane) & 1u) ? lg : -1e30f;
            m[q] = fmaxf(m[q], lm);
        }
    }
#pragma unroll
    for (int q = 0; q < 4; q++)
#pragma unroll
        for (int off = 16; off; off >>= 1)
            m[q] = fmaxf(m[q], __shfl_xor_sync(0xffffffffu, m[q], off));

    // ---- pass 2: denominator ----
    for (int k = 0; k < NW; k++) {
        float2 ss = s_ss[k * 32 + lane];
#pragma unroll
        for (int q = 0; q < 4; q++) {
            unsigned word = g_adjbits[(i0 + q) * NW + k];
            float lg = lrelu(dstv[q] + ss.x) + ss.y;
            if ((word >> lane) & 1u) dn[q] += __expf(lg - m[q]);
        }
    }
#pragma unroll
    for (int q = 0; q < 4; q++) {
#pragma unroll
        for (int off = 16; off; off >>= 1)
            dn[q] += __shfl_xor_sync(0xffffffffu, dn[q], off);
        dn[q] = fmaxf(dn[q], 1.1920929e-7f);   // eps, matches reference
    }

    // ---- pass 3: tiled weighted aggregation ----
    unsigned long long acc01 = 0ull, acc23 = 0ull;   // packed fp32 pairs
    const float* gP = g_proj + bh * N_ * O_;
    for (int t = 0; t < N_ / TJ; t++) {
        __syncthreads();   // previous tile fully consumed
        const float4* src4 = (const float4*)(gP + t * TJ * O_);
        float4* dst4 = (float4*)s_P;
#pragma unroll
        for (int u = 0; u < 4; u++) dst4[tid + u * 256] = src4[tid + u * 256];

        // recompute exp weights for this tile (independent of s_P)
#pragma unroll
        for (int k = 0; k < 4; k++) {
            int jt = k * 32 + lane;
            float2 ss = s_ss[t * TJ + jt];
            float4 e4;
            float* ep = (float*)&e4;
#pragma unroll
            for (int q = 0; q < 4; q++) {
                unsigned word = g_adjbits[(i0 + q) * NW + t * 4 + k];
                float lg = lrelu(dstv[q] + ss.x) + ss.y;
                ep[q] = ((word >> lane) & 1u) ? __expf(lg - m[q]) : 0.f;
            }
            s_e[w * TJ + jt] = e4;
        }
        __syncthreads();

#pragma unroll 4
        for (int j = 0; j < TJ; j++) {
            float4 e4 = s_e[w * TJ + j];           // LDS.128 broadcast
            float  pv = s_P[j * O_ + lane];        // conflict-free
            unsigned long long pv2 = pack2(pv, pv);
            fma2(acc01, pack2(e4.x, e4.y), pv2);
            fma2(acc23, pack2(e4.z, e4.w), pv2);
        }
    }

    float a0, a1, a2, a3;
    unpack2(acc01, a0, a1);
    unpack2(acc23, a2, a3);
    float res[4] = { a0 / dn[0], a1 / dn[1], a2 / dn[2], a3 / dn[3] };
#pragma unroll
    for (int q = 0; q < 4; q++) {
        int i = i0 + q;
        out[(b * N_ + i) * (H_ * O_) + h * O_ + lane] = res[q];
    }
}

// ---------------- launch ----------------
extern "C" void kernel_launch(void* const* d_in, const int* in_sizes, int n_in,
                              void* d_out, int out_size) {
    const float* x        = (const float*)d_in[0];
    const int*   adj      = (const int*)  d_in[1];
    const float* prior    = (const float*)d_in[2];
    const float* beta     = (const float*)d_in[3];
    const float* weight   = (const float*)d_in[4];
    const float* attn_src = (const float*)d_in[5];
    const float* attn_dst = (const float*)d_in[6];
    const float* bias     = (const float*)d_in[7];
    float* out = (float*)d_out;

    k0_pack<<<4096, 256>>>(adj);                 // 32768 warps == 1024*32 words
    k1_proj<<<B_ * N_, 128>>>(x, weight, bias, attn_src, attn_dst, beta, prior);
    k2_attn<<<dim3(N_ / 32, H_, B_), 256>>>(out);
}

// round 2
// speedup vs baseline: 1.3448x; 1.3448x over previous
#include <cuda_runtime.h>

#define B_ 8
#define N_ 1024
#define I_ 64
#define O_ 32
#define H_ 4
#define NW 32            // adjacency words per row
#define RPW 16           // dst rows per warp in k2
#define WPB 4            // warps per block in k2
#define ROWS_PB (RPW*WPB)

// ---- device scratch ----
__device__ float    g_proj[B_*H_*N_*O_];   // [b][h][j][o]
__device__ float2   g_srcsp[B_*H_*N_];     // (src_score, gain*prior)
__device__ float    g_dstsc[B_*H_*N_];
__device__ unsigned g_adjbits[N_*NW];

__device__ __forceinline__ unsigned long long pack2(float a, float b) {
    unsigned long long r;
    asm("mov.b64 %0, {%1, %2};" : "=l"(r) : "f"(a), "f"(b));
    return r;
}
__device__ __forceinline__ void fma2(unsigned long long& d, unsigned long long a, unsigned long long b) {
    asm("fma.rn.f32x2 %0, %1, %2, %3;" : "=l"(d) : "l"(a), "l"(b), "l"(d));
}
__device__ __forceinline__ void unpack2(unsigned long long v, float& a, float& b) {
    asm("mov.b64 {%0, %1}, %2;" : "=f"(a), "=f"(b) : "l"(v));
}

// ---------------- K01: adjacency pack (blocks 0..1023) + projection (1024..1279) ----------------
__global__ __launch_bounds__(256) void k01_prep(
    const int* __restrict__ adj,
    const float* __restrict__ x, const float* __restrict__ weight,
    const float* __restrict__ bias, const float* __restrict__ attn_src,
    const float* __restrict__ attn_dst, const float* __restrict__ beta,
    const float* __restrict__ prior)
{
    __shared__ float s_x[32*I_];           // 8KB (proj role only)
    int tid = threadIdx.x, lane = tid & 31, w = tid >> 5;

    if (blockIdx.x < 1024) {
        // ---- pack: warp handles 4 adjacency words, MLP=4 ----
        int gw = blockIdx.x * 8 + w;       // [0,8192)
        int i  = gw >> 3;                  // row
        int k0 = (gw & 7) * 4;             // word base
#pragma unroll
        for (int c = 0; c < 4; c++) {
            int v = adj[i*N_ + (k0+c)*32 + lane];
            unsigned bits = __ballot_sync(0xffffffffu, v != 0);
            if (lane == c) g_adjbits[i*NW + k0 + c] = bits;
        }
        return;
    }

    // ---- projection: 32 nodes per block, weight column in registers ----
    int pb = blockIdx.x - 1024;            // [0,256)
    int g0 = pb * 32;                      // first global node (b*N+n)
    int b  = g0 >> 10;
    int half = tid >> 7;                   // 0/1: which 16 nodes
    int ho = tid & 127;
    int h  = ho >> 5, o = ho & 31;

    // x tile -> smem (2048 floats)
    const float4* gx4 = (const float4*)(x + g0 * I_);
    ((float4*)s_x)[tid]       = gx4[tid];
    ((float4*)s_x)[tid + 256] = gx4[tid + 256];

    // weight column in registers
    float wr[I_];
    const float* wp = weight + h*I_*O_ + o;
#pragma unroll
    for (int i = 0; i < I_; i++) wr[i] = wp[i*O_];
    float bias_v = bias[ho];
    float asrc   = attn_src[ho];
    float adst   = attn_dst[ho];
    float bt     = beta[h];
    float gain   = (bt > 20.f) ? bt : log1pf(__expf(bt));
    int bh = b*H_ + h;
    __syncthreads();

    for (int q = 0; q < 16; q++) {
        int nl = half*16 + q;              // local node
        int g  = g0 + nl;
        int n  = g & 1023;
        float acc = bias_v;
        const float4* xs4 = (const float4*)(s_x + nl*I_);
#pragma unroll
        for (int i4 = 0; i4 < I_/4; i4++) {
            float4 xv = xs4[i4];
            acc = fmaf(xv.x, wr[i4*4+0], acc);
            acc = fmaf(xv.y, wr[i4*4+1], acc);
            acc = fmaf(xv.z, wr[i4*4+2], acc);
            acc = fmaf(xv.w, wr[i4*4+3], acc);
        }
        g_proj[(bh*N_ + n)*O_ + o] = acc;

        float s = acc * asrc;
        float d = acc * adst;
#pragma unroll
        for (int off = 16; off; off >>= 1) {
            s += __shfl_xor_sync(0xffffffffu, s, off);
            d += __shfl_xor_sync(0xffffffffu, d, off);
        }
        if (o == 0) {
            int idx = bh*N_ + n;
            g_dstsc[idx] = d;
            g_srcsp[idx] = make_float2(s, gain * prior[g]);
        }
    }
}

// ---------------- K2: single-pass fused softmax + aggregation ----------------
// grid (16, H, B), 128 threads. warp owns 16 dst rows; lanes = o.
__global__ __launch_bounds__(128, 4) void k2_attn(float* __restrict__ out) {
    __shared__ float  s_P[128*O_];         // 16KB projected j-tile
    __shared__ float4 s_e[WPB][4][32];     // 8KB per-warp exp staging [rg][j]

    int tid = threadIdx.x, lane = tid & 31, w = tid >> 5;
    int h = blockIdx.y, b = blockIdx.z;
    int bh = b*H_ + h;
    int rowbase = blockIdx.x * ROWS_PB + w * RPW;

    float dstv[RPW];
#pragma unroll
    for (int r = 0; r < RPW; r++) dstv[r] = g_dstsc[bh*N_ + rowbase + r];

    unsigned long long acc[RPW/2];
#pragma unroll
    for (int p = 0; p < RPW/2; p++) acc[p] = 0ull;
    float dn[RPW];
#pragma unroll
    for (int r = 0; r < RPW; r++) dn[r] = 0.f;

    const float4* gP4 = (const float4*)(g_proj + bh*N_*O_);
    const float2* gss = g_srcsp + bh*N_;

    for (int t = 0; t < N_/128; t++) {
        __syncthreads();
#pragma unroll
        for (int u = 0; u < 8; u++)
            ((float4*)s_P)[tid + u*128] = gP4[t*1024 + tid + u*128];
        __syncthreads();

        for (int c = 0; c < 4; c++) {
            // ---- compute e for 32 j's (lane = j), all 16 rows ----
            int jt = t*128 + c*32 + lane;
            float2 ss = gss[jt];
            int widx = t*4 + c;
            float e[RPW];
#pragma unroll
            for (int r = 0; r < RPW; r++) {
                unsigned word = g_adjbits[(rowbase + r)*NW + widx];   // uniform LDG
                float v  = dstv[r] + ss.x;
                float lg = (v > 0.f ? v : 0.2f*v) + ss.y;
                float ev = ((word >> lane) & 1u) ? __expf(lg) : 0.f;
                e[r] = ev;
                dn[r] += ev;
            }
#pragma unroll
            for (int rg = 0; rg < 4; rg++)
                s_e[w][rg][lane] = make_float4(e[rg*4+0], e[rg*4+1], e[rg*4+2], e[rg*4+3]);
            __syncwarp();

            // ---- aggregate 32 j's (lane = o) ----
#pragma unroll 4
            for (int j = 0; j < 32; j++) {
                float pv = s_P[(c*32 + j)*O_ + lane];
                unsigned long long pv2 = pack2(pv, pv);
                float4 e0 = s_e[w][0][j];
                float4 e1 = s_e[w][1][j];
                float4 e2 = s_e[w][2][j];
                float4 e3 = s_e[w][3][j];
                fma2(acc[0], pack2(e0.x, e0.y), pv2);
                fma2(acc[1], pack2(e0.z, e0.w), pv2);
                fma2(acc[2], pack2(e1.x, e1.y), pv2);
                fma2(acc[3], pack2(e1.z, e1.w), pv2);
                fma2(acc[4], pack2(e2.x, e2.y), pv2);
                fma2(acc[5], pack2(e2.z, e2.w), pv2);
                fma2(acc[6], pack2(e3.x, e3.y), pv2);
                fma2(acc[7], pack2(e3.z, e3.w), pv2);
            }
            __syncwarp();
        }
    }

    // reduce dn across lanes (each lane covered j = lane mod 32)
#pragma unroll
    for (int r = 0; r < RPW; r++)
#pragma unroll
        for (int off = 16; off; off >>= 1)
            dn[r] += __shfl_xor_sync(0xffffffffu, dn[r], off);

#pragma unroll
    for (int p = 0; p < RPW/2; p++) {
        float a0, a1; unpack2(acc[p], a0, a1);
        int r0 = 2*p;
        float i0 = dn[r0]   > 0.f ? 1.f/dn[r0]   : 0.f;
        float i1 = dn[r0+1] > 0.f ? 1.f/dn[r0+1] : 0.f;
        int row = rowbase + r0;
        out[(b*N_ + row    )*(H_*O_) + h*O_ + lane] = a0*i0;
        out[(b*N_ + row + 1)*(H_*O_) + h*O_ + lane] = a1*i1;
    }
}

// ---------------- launch ----------------
extern "C" void kernel_launch(void* const* d_in, const int* in_sizes, int n_in,
                              void* d_out, int out_size) {
    const float* x        = (const float*)d_in[0];
    const int*   adj      = (const int*)  d_in[1];
    const float* prior    = (const float*)d_in[2];
    const float* beta     = (const float*)d_in[3];
    const float* weight   = (const float*)d_in[4];
    const float* attn_src = (const float*)d_in[5];
    const float* attn_dst = (const float*)d_in[6];
    const float* bias     = (const float*)d_in[7];
    float* out = (float*)d_out;

    k01_prep<<<1280, 256>>>(adj, x, weight, bias, attn_src, attn_dst, beta, prior);
    k2_attn<<<dim3(N_/ROWS_PB, H_, B_), 128>>>(out);
}

// round 4
// speedup vs baseline: 2.1920x; 1.6300x over previous
#include <cuda_runtime.h>
#include <cstdint>

#define B_ 8
#define N_ 1024
#define I_ 64
#define O_ 32
#define H_ 4
#define NW 32
#define PS 40              // padded P-tile row stride (floats): bank = 8q+g, conflict-free

// ---- device scratch ----
__device__ float    g_proj[B_*H_*N_*O_];    // [bh][j][o]
__device__ float2   g_srcsp[B_*H_*N_];      // (src_score, gain*prior)
__device__ float    g_dstsc[B_*H_*N_];
__device__ unsigned g_adjbits[N_*NW];

__device__ __forceinline__ float tf32r(float x) {
    uint32_t r;
    asm("cvt.rna.tf32.f32 %0, %1;" : "=r"(r) : "f"(x));
    return __uint_as_float(r);
}

// =============== K01: adjacency pack (blocks 0..127) + projection (128..383) ===============
__global__ __launch_bounds__(256) void k01_prep(
    const int* __restrict__ adj,
    const float* __restrict__ x, const float* __restrict__ weight,
    const float* __restrict__ bias, const float* __restrict__ attn_src,
    const float* __restrict__ attn_dst, const float* __restrict__ beta,
    const float* __restrict__ prior)
{
    __shared__ float s_x[32*I_];          // 8KB
    int tid = threadIdx.x, lane = tid & 31, w = tid >> 5;

    if (blockIdx.x < 128) {
        // ---- pack: warp handles one adjacency row via int4 + REDUX.OR ----
        int i = blockIdx.x * 8 + w;
        const int4* a4 = (const int4*)(adj + (size_t)i * N_);
        int g = lane >> 3;
        unsigned gmask = 0xFFu << (g * 8);
        int sh = (lane & 7) * 4;
#pragma unroll
        for (int c4 = 0; c4 < 8; c4++) {
            int4 v = a4[c4 * 32 + lane];
            unsigned nib = (unsigned)(v.x != 0) | ((unsigned)(v.y != 0) << 1)
                         | ((unsigned)(v.z != 0) << 2) | ((unsigned)(v.w != 0) << 3);
            unsigned word = __reduce_or_sync(gmask, nib << sh);
            if ((lane & 7) == 0) g_adjbits[i * NW + c4 * 4 + g] = word;
        }
        return;
    }

    // ---- projection: 32 nodes per block, weight column in registers ----
    int pb = blockIdx.x - 128;             // [0,256)
    int g0 = pb * 32;                      // first (b*N+n)
    int b  = g0 >> 10;
    int half = tid >> 7;
    int ho = tid & 127;
    int h = ho >> 5, o = ho & 31;

    const float4* gx4 = (const float4*)(x + (size_t)g0 * I_);
    ((float4*)s_x)[tid]       = gx4[tid];
    ((float4*)s_x)[tid + 256] = gx4[tid + 256];

    float wr[I_];
    const float* wp = weight + h * I_ * O_ + o;
#pragma unroll
    for (int i = 0; i < I_; i++) wr[i] = wp[i * O_];
    float bias_v = bias[ho], asrc = attn_src[ho], adst = attn_dst[ho];
    float bt = beta[h];
    float gain = (bt > 20.f) ? bt : log1pf(__expf(bt));
    int bh = b * H_ + h;
    __syncthreads();

    for (int q = 0; q < 16; q++) {
        int nl = half * 16 + q;
        int gidx = g0 + nl, n = gidx & 1023;
        float acc = bias_v;
        const float4* xs4 = (const float4*)(s_x + nl * I_);
#pragma unroll
        for (int i4 = 0; i4 < I_/4; i4++) {
            float4 xv = xs4[i4];
            acc = fmaf(xv.x, wr[4*i4+0], acc);
            acc = fmaf(xv.y, wr[4*i4+1], acc);
            acc = fmaf(xv.z, wr[4*i4+2], acc);
            acc = fmaf(xv.w, wr[4*i4+3], acc);
        }
        g_proj[((size_t)bh * N_ + n) * O_ + o] = acc;
        float s = acc * asrc, d = acc * adst;
#pragma unroll
        for (int off = 16; off; off >>= 1) {
            s += __shfl_xor_sync(0xffffffffu, s, off);
            d += __shfl_xor_sync(0xffffffffu, d, off);
        }
        if (o == 0) {
            int idx = bh * N_ + n;
            g_dstsc[idx] = d;
            g_srcsp[idx] = make_float2(s, gain * prior[gidx]);
        }
    }
}

// =============== K2: register-fragment exp -> mma.sync tf32, fused softmax ===============
// grid (8, H, B), 256 threads. Block: 128 dst rows of one bh. Warp: 16 rows (m16).
__global__ __launch_bounds__(256) void k2_attn(float* __restrict__ out) {
    __shared__ float2 s_ss[N_];            // 8KB  (src, gain*prior)
    __shared__ float  s_P[128*PS];         // 20KB padded P tile

    int tid = threadIdx.x, lane = tid & 31, w = tid >> 5;
    int h = blockIdx.y, b = blockIdx.z, bh = b * H_ + h;
    int row0 = blockIdx.x * 128;

    const float2* gss = g_srcsp + (size_t)bh * N_;
#pragma unroll
    for (int u = 0; u < 4; u++) s_ss[tid + u * 256] = gss[tid + u * 256];

    int g  = lane >> 2;                    // 0..7 row group
    int q4 = lane & 3;                     // 0..3 k slot
    int r_lo = w * 16 + g, r_hi = r_lo + 8;
    float dst_lo = g_dstsc[(size_t)bh * N_ + row0 + r_lo];
    float dst_hi = g_dstsc[(size_t)bh * N_ + row0 + r_hi];
    const unsigned* adj_lo = g_adjbits + (size_t)(row0 + r_lo) * NW;
    const unsigned* adj_hi = g_adjbits + (size_t)(row0 + r_hi) * NW;

    float acc[4][4];
#pragma unroll
    for (int nc = 0; nc < 4; nc++)
#pragma unroll
        for (int k = 0; k < 4; k++) acc[nc][k] = 0.f;
    float dn_lo = 0.f, dn_hi = 0.f;

    const float4* gp4 = (const float4*)(g_proj + (size_t)bh * N_ * O_);

    for (int t = 0; t < N_/128; t++) {
        __syncthreads();
        // stage P tile (tf32-rounded) with padded stride
#pragma unroll
        for (int u = 0; u < 4; u++) {
            int idx = tid + u * 256;               // 1024 float4 = 128 j x 32 o
            int j = idx >> 3, o4 = idx & 7;
            float4 v = gp4[t * 1024 + idx];
            v.x = tf32r(v.x); v.y = tf32r(v.y); v.z = tf32r(v.z); v.w = tf32r(v.w);
            *(float4*)(s_P + j * PS + o4 * 4) = v;
        }
        __syncthreads();

        unsigned word_lo = 0, word_hi = 0;
#pragma unroll 4
        for (int kc = 0; kc < 16; kc++) {
            if ((kc & 3) == 0) {
                int widx = t * 4 + (kc >> 2);
                word_lo = adj_lo[widx];
                word_hi = adj_hi[widx];
            }
            int jb = kc * 8;
            float2 ss0 = s_ss[t * 128 + jb + q4];
            float2 ss1 = s_ss[t * 128 + jb + q4 + 4];
            int bit0 = ((kc & 3) << 3) + q4;

            float v0l = dst_lo + ss0.x, v0h = dst_hi + ss0.x;
            float v1l = dst_lo + ss1.x, v1h = dst_hi + ss1.x;
            float e0 = ((word_lo >> bit0) & 1u)       ? __expf(fmaxf(v0l, 0.2f*v0l) + ss0.y) : 0.f;
            float e1 = ((word_hi >> bit0) & 1u)       ? __expf(fmaxf(v0h, 0.2f*v0h) + ss0.y) : 0.f;
            float e2 = ((word_lo >> (bit0 + 4)) & 1u) ? __expf(fmaxf(v1l, 0.2f*v1l) + ss1.y) : 0.f;
            float e3 = ((word_hi >> (bit0 + 4)) & 1u) ? __expf(fmaxf(v1h, 0.2f*v1h) + ss1.y) : 0.f;
            e0 = tf32r(e0); e1 = tf32r(e1); e2 = tf32r(e2); e3 = tf32r(e3);
            dn_lo += e0 + e2;
            dn_hi += e1 + e3;

            uint32_t a0 = __float_as_uint(e0), a1 = __float_as_uint(e1);
            uint32_t a2 = __float_as_uint(e2), a3 = __float_as_uint(e3);
            const float* Pj0 = s_P + (jb + q4) * PS + g;
            const float* Pj1 = Pj0 + 4 * PS;
#pragma unroll
            for (int nc = 0; nc < 4; nc++) {
                uint32_t b0 = __float_as_uint(Pj0[nc * 8]);
                uint32_t b1 = __float_as_uint(Pj1[nc * 8]);
                asm volatile(
                    "mma.sync.aligned.m16n8k8.row.col.f32.tf32.tf32.f32 "
                    "{%0,%1,%2,%3}, {%4,%5,%6,%7}, {%8,%9}, {%0,%1,%2,%3};"
                    : "+f"(acc[nc][0]), "+f"(acc[nc][1]), "+f"(acc[nc][2]), "+f"(acc[nc][3])
                    : "r"(a0), "r"(a1), "r"(a2), "r"(a3), "r"(b0), "r"(b1));
            }
        }
    }

    // quad-reduce dn (rows live in 4-lane groups)
#pragma unroll
    for (int off = 1; off <= 2; off <<= 1) {
        dn_lo += __shfl_xor_sync(0xffffffffu, dn_lo, off);
        dn_hi += __shfl_xor_sync(0xffffffffu, dn_hi, off);
    }
    float inv_lo = dn_lo > 0.f ? 1.f / dn_lo : 0.f;
    float inv_hi = dn_hi > 0.f ? 1.f / dn_hi : 0.f;

    float* orow_lo = out + ((size_t)b * N_ + row0 + r_lo) * (H_ * O_) + h * O_;
    float* orow_hi = out + ((size_t)b * N_ + row0 + r_hi) * (H_ * O_) + h * O_;
#pragma unroll
    for (int nc = 0; nc < 4; nc++) {
        float2 vlo = make_float2(acc[nc][0] * inv_lo, acc[nc][1] * inv_lo);
        float2 vhi = make_float2(acc[nc][2] * inv_hi, acc[nc][3] * inv_hi);
        *(float2*)(orow_lo + nc * 8 + 2 * q4) = vlo;
        *(float2*)(orow_hi + nc * 8 + 2 * q4) = vhi;
    }
}

// =============== launch ===============
extern "C" void kernel_launch(void* const* d_in, const int* in_sizes, int n_in,
                              void* d_out, int out_size) {
    const float* x        = (const float*)d_in[0];
    const int*   adj      = (const int*)  d_in[1];
    const float* prior    = (const float*)d_in[2];
    const float* beta     = (const float*)d_in[3];
    const float* weight   = (const float*)d_in[4];
    const float* attn_src = (const float*)d_in[5];
    const float* attn_dst = (const float*)d_in[6];
    const float* bias     = (const float*)d_in[7];
    float* out = (float*)d_out;

    k01_prep<<<384, 256>>>(adj, x, weight, bias, attn_src, attn_dst, beta, prior);
    k2_attn<<<dim3(N_/128, H_, B_), 256>>>(out);
}

// round 5
// speedup vs baseline: 2.6850x; 1.2249x over previous
#include <cuda_runtime.h>
#include <cstdint>

#define B_ 8
#define N_ 1024
#define I_ 64
#define O_ 32
#define H_ 4
#define NW 32
#define PS 40              // padded P-tile row stride: bank(8q4+g) conflict-free
#define LOG2E 1.4426950408889634f

// ---- device scratch ----
__device__ float    g_proj[B_*H_*N_*O_];    // [bh][j][o], tf32-rounded
__device__ float2   g_srcsp[B_*H_*N_];      // (src*L, gain*prior*L)
__device__ float    g_dstsc[B_*H_*N_];      // dst*L
__device__ unsigned g_adjbits[N_*NW];

__device__ __forceinline__ float tf32r(float x) {
    uint32_t r;
    asm("cvt.rna.tf32.f32 %0, %1;" : "=r"(r) : "f"(x));
    return __uint_as_float(r);
}
__device__ __forceinline__ float ex2f(float x) {
    float r;
    asm("ex2.approx.f32 %0, %1;" : "=f"(r) : "f"(x));
    return r;
}

// =============== K01: pack (blocks 0..127) + projection/scores (128..383) ===============
__global__ __launch_bounds__(256) void k01_prep(
    const int* __restrict__ adj,
    const float* __restrict__ x, const float* __restrict__ weight,
    const float* __restrict__ bias, const float* __restrict__ attn_src,
    const float* __restrict__ attn_dst, const float* __restrict__ beta,
    const float* __restrict__ prior)
{
    __shared__ float s_x[32*I_];           // 8KB
    __shared__ float s_ws[H_*I_];          // 1KB  w_src scaled
    __shared__ float s_wd[H_*I_];          // 1KB  w_dst scaled
    __shared__ float s_c[8];               // score consts (bias terms), scaled
    int tid = threadIdx.x, lane = tid & 31, w = tid >> 5;

    if (blockIdx.x < 128) {
        // ---- pack one adjacency row per warp (int4 + REDUX.OR) ----
        int i = blockIdx.x * 8 + w;
        const int4* a4 = (const int4*)(adj + (size_t)i * N_);
        int g = lane >> 3;
        unsigned gmask = 0xFFu << (g * 8);
        int sh = (lane & 7) * 4;
#pragma unroll
        for (int c4 = 0; c4 < 8; c4++) {
            int4 v = a4[c4 * 32 + lane];
            unsigned nib = (unsigned)(v.x != 0) | ((unsigned)(v.y != 0) << 1)
                         | ((unsigned)(v.z != 0) << 2) | ((unsigned)(v.w != 0) << 3);
            unsigned word = __reduce_or_sync(gmask, nib << sh);
            if ((lane & 7) == 0) g_adjbits[i * NW + c4 * 4 + g] = word;
        }
        return;
    }

    int pb = blockIdx.x - 128;             // [0,256)
    int g0 = pb * 32;                      // first (b*N+n)
    int b  = g0 >> 10;

    // stage x tile
    const float4* gx4 = (const float4*)(x + (size_t)g0 * I_);
    ((float4*)s_x)[tid]       = gx4[tid];
    ((float4*)s_x)[tid + 256] = gx4[tid + 256];

    // w_src[h,i] = L * sum_o W[h,i,o]*attn_src[h,o]   (tid -> (h,i))
    {
        int h = tid >> 6;
        const float4* wrow = (const float4*)(weight + (size_t)tid * O_);
        const float4* as4  = (const float4*)(attn_src + h * O_);
        const float4* ad4  = (const float4*)(attn_dst + h * O_);
        float accs = 0.f, accd = 0.f;
#pragma unroll
        for (int o4 = 0; o4 < 8; o4++) {
            float4 wv = wrow[o4], av = as4[o4], dv = ad4[o4];
            accs += wv.x*av.x + wv.y*av.y + wv.z*av.z + wv.w*av.w;
            accd += wv.x*dv.x + wv.y*dv.y + wv.z*dv.z + wv.w*dv.w;
        }
        s_ws[tid] = accs * LOG2E;
        s_wd[tid] = accd * LOG2E;
    }
    if (tid < 8) {                          // bias contribution to scores
        int hh = tid & 3;
        const float* bb = bias + hh * O_;
        const float* aa = (tid < 4 ? attn_src : attn_dst) + hh * O_;
        float c = 0.f;
#pragma unroll
        for (int o = 0; o < O_; o++) c += bb[o] * aa[o];
        s_c[tid] = c * LOG2E;
    }
    __syncthreads();

    // ---- projection: thread = (half, h, o), 16 nodes each; store tf32-rounded ----
    {
        int half = tid >> 7, ho = tid & 127;
        int h = ho >> 5, o = ho & 31;
        float wr[I_];
        const float* wp = weight + h * I_ * O_ + o;
#pragma unroll
        for (int i = 0; i < I_; i++) wr[i] = wp[i * O_];
        float bias_v = bias[ho];
        int bh = b * H_ + h;
        for (int q = 0; q < 16; q++) {
            int nl = half * 16 + q;
            int n = (g0 + nl) & 1023;
            float acc = bias_v;
            const float4* xs4 = (const float4*)(s_x + nl * I_);
#pragma unroll
            for (int i4 = 0; i4 < I_/4; i4++) {
                float4 xv = xs4[i4];
                acc = fmaf(xv.x, wr[4*i4+0], acc);
                acc = fmaf(xv.y, wr[4*i4+1], acc);
                acc = fmaf(xv.z, wr[4*i4+2], acc);
                acc = fmaf(xv.w, wr[4*i4+3], acc);
            }
            g_proj[((size_t)bh * N_ + n) * O_ + o] = tf32r(acc);
        }
    }

    // ---- scores: thread = (role, n, h); no shuffles ----
    {
        int role = tid >> 7;               // 0: src, 1: dst
        int n = (tid & 127) >> 2, hs = tid & 3;
        const float4* xv4 = (const float4*)(s_x + n * I_);
        const float4* wv4 = (const float4*)((role ? s_wd : s_ws) + hs * I_);
        float sc = s_c[role * 4 + hs];
#pragma unroll
        for (int i4 = 0; i4 < I_/4; i4++) {
            float4 xv = xv4[i4], wv = wv4[i4];
            sc += xv.x*wv.x + xv.y*wv.y + xv.z*wv.z + xv.w*wv.w;
        }
        int gidx = g0 + n;
        int idx = (b * H_ + hs) * N_ + (gidx & 1023);
        if (role) {
            g_dstsc[idx] = sc;
        } else {
            float bt = beta[hs];
            float gain = ((bt > 20.f) ? bt : log1pf(__expf(bt))) * LOG2E;
            g_srcsp[idx] = make_float2(sc, gain * prior[gidx]);
        }
    }
}

// =============== K2: 2-way j-split, register-fragment exp -> mma.sync tf32 ===============
// grid (16, H, B), 256 threads. Block: 64 dst rows. Warp groups 0/1 split j halves.
__global__ __launch_bounds__(256) void k2_attn(float* __restrict__ out) {
    __shared__ union {
        float2 ss[N_];                     // (src*L, gain*prior*L)
        float  red[2048];                  // grp1 partial acc (4w x 32l x 16)
    } s_u;
    __shared__ float s_dn[256];            // grp1 partial dn
    __shared__ float s_P[2][128*PS];       // 40KB: per-group P tile

    int tid = threadIdx.x, lane = tid & 31, w = tid >> 5;
    int h = blockIdx.y, b = blockIdx.z, bh = b * H_ + h;
    int row0 = blockIdx.x * 64;

    const float2* gss = g_srcsp + (size_t)bh * N_;
#pragma unroll
    for (int u = 0; u < 4; u++) s_u.ss[tid + u * 256] = gss[tid + u * 256];
    __syncthreads();

    int grp = w >> 2;                      // j-half
    int g   = lane >> 2;                   // 0..7 row group
    int q4  = lane & 3;                    // k slot
    int r_lo = (w & 3) * 16 + g, r_hi = r_lo + 8;
    float dst_lo = g_dstsc[(size_t)bh * N_ + row0 + r_lo];
    float dst_hi = g_dstsc[(size_t)bh * N_ + row0 + r_hi];
    const unsigned* adj_lo = g_adjbits + (size_t)(row0 + r_lo) * NW;
    const unsigned* adj_hi = g_adjbits + (size_t)(row0 + r_hi) * NW;

    float acc[4][4];
#pragma unroll
    for (int nc = 0; nc < 4; nc++)
#pragma unroll
        for (int k = 0; k < 4; k++) acc[nc][k] = 0.f;
    float dn_lo = 0.f, dn_hi = 0.f;

    const float4* gp4 = (const float4*)(g_proj + (size_t)bh * N_ * O_);
    float* Pbuf = s_P[grp];
    int lt = tid & 127;                    // group-local tid
    int barid = grp + 1;

    for (int tt = 0; tt < 4; tt++) {
        int t = grp * 4 + tt;              // global tile
        if (tt) asm volatile("bar.sync %0, %1;" :: "r"(barid), "r"(128) : "memory");
        // stage P tile (already tf32-rounded)
#pragma unroll
        for (int u = 0; u < 8; u++) {
            int idx = lt + u * 128;        // 1024 float4
            int j = idx >> 3, o4 = idx & 7;
            *(float4*)(Pbuf + j * PS + o4 * 4) = gp4[t * 1024 + idx];
        }
        asm volatile("bar.sync %0, %1;" :: "r"(barid), "r"(128) : "memory");

#pragma unroll
        for (int w4 = 0; w4 < 4; w4++) {
            unsigned wl = adj_lo[t * 4 + w4] >> q4;
            unsigned wh = adj_hi[t * 4 + w4] >> q4;
#pragma unroll
            for (int sub = 0; sub < 4; sub++) {
                int jb = (w4 * 4 + sub) * 8;
                float2 ss0 = s_u.ss[t * 128 + jb + q4];
                float2 ss1 = s_u.ss[t * 128 + jb + q4 + 4];

                // logit = 0.6v + 0.4|v| + prior   (== lrelu(v)+prior, all *log2e)
                float v0l = dst_lo + ss0.x, v0h = dst_hi + ss0.x;
                float v1l = dst_lo + ss1.x, v1h = dst_hi + ss1.x;
                float a0 = fmaf(0.4f, fabsf(v0l), fmaf(0.6f, v0l, ss0.y));
                float a1 = fmaf(0.4f, fabsf(v0h), fmaf(0.6f, v0h, ss0.y));
                float a2 = fmaf(0.4f, fabsf(v1l), fmaf(0.6f, v1l, ss1.y));
                float a3 = fmaf(0.4f, fabsf(v1h), fmaf(0.6f, v1h, ss1.y));

                float e0 = ((wl >> (sub * 8)) & 1u)     ? ex2f(a0) : 0.f;
                float e1 = ((wh >> (sub * 8)) & 1u)     ? ex2f(a1) : 0.f;
                float e2 = ((wl >> (sub * 8 + 4)) & 1u) ? ex2f(a2) : 0.f;
                float e3 = ((wh >> (sub * 8 + 4)) & 1u) ? ex2f(a3) : 0.f;
                e0 = tf32r(e0); e1 = tf32r(e1); e2 = tf32r(e2); e3 = tf32r(e3);
                dn_lo += e0 + e2;
                dn_hi += e1 + e3;

                uint32_t u0 = __float_as_uint(e0), u1 = __float_as_uint(e1);
                uint32_t u2 = __float_as_uint(e2), u3 = __float_as_uint(e3);
                const float* Pj0 = Pbuf + (jb + q4) * PS + g;
                const float* Pj1 = Pj0 + 4 * PS;
#pragma unroll
                for (int nc = 0; nc < 4; nc++) {
                    uint32_t b0 = __float_as_uint(Pj0[nc * 8]);
                    uint32_t b1 = __float_as_uint(Pj1[nc * 8]);
                    asm volatile(
                        "mma.sync.aligned.m16n8k8.row.col.f32.tf32.tf32.f32 "
                        "{%0,%1,%2,%3}, {%4,%5,%6,%7}, {%8,%9}, {%0,%1,%2,%3};"
                        : "+f"(acc[nc][0]), "+f"(acc[nc][1]), "+f"(acc[nc][2]), "+f"(acc[nc][3])
                        : "r"(u0), "r"(u1), "r"(u2), "r"(u3), "r"(b0), "r"(b1));
                }
            }
        }
    }

    // ---- merge j-halves ----
    __syncthreads();
    if (grp == 1) {
        int base = (w & 3) * 32 + lane;
        float* ra = s_u.red + base * 16;
#pragma unroll
        for (int nc = 0; nc < 4; nc++)
#pragma unroll
            for (int k = 0; k < 4; k++) ra[nc * 4 + k] = acc[nc][k];
        s_dn[base * 2] = dn_lo;
        s_dn[base * 2 + 1] = dn_hi;
    }
    __syncthreads();
    if (grp == 0) {
        int base = (w & 3) * 32 + lane;
        const float* ra = s_u.red + base * 16;
#pragma unroll
        for (int nc = 0; nc < 4; nc++)
#pragma unroll
            for (int k = 0; k < 4; k++) acc[nc][k] += ra[nc * 4 + k];
        dn_lo += s_dn[base * 2];
        dn_hi += s_dn[base * 2 + 1];
#pragma unroll
        for (int off = 1; off <= 2; off <<= 1) {
            dn_lo += __shfl_xor_sync(0xffffffffu, dn_lo, off);
            dn_hi += __shfl_xor_sync(0xffffffffu, dn_hi, off);
        }
        float inv_lo = dn_lo > 0.f ? 1.f / dn_lo : 0.f;
        float inv_hi = dn_hi > 0.f ? 1.f / dn_hi : 0.f;

        float* orow_lo = out + ((size_t)b * N_ + row0 + r_lo) * (H_ * O_) + h * O_;
        float* orow_hi = out + ((size_t)b * N_ + row0 + r_hi) * (H_ * O_) + h * O_;
#pragma unroll
        for (int nc = 0; nc < 4; nc++) {
            float2 vlo = make_float2(acc[nc][0] * inv_lo, acc[nc][1] * inv_lo);
            float2 vhi = make_float2(acc[nc][2] * inv_hi, acc[nc][3] * inv_hi);
            *(float2*)(orow_lo + nc * 8 + 2 * q4) = vlo;
            *(float2*)(orow_hi + nc * 8 + 2 * q4) = vhi;
        }
    }
}

// =============== launch ===============
extern "C" void kernel_launch(void* const* d_in, const int* in_sizes, int n_in,
                              void* d_out, int out_size) {
    const float* x        = (const float*)d_in[0];
    const int*   adj      = (const int*)  d_in[1];
    const float* prior    = (const float*)d_in[2];
    const float* beta     = (const float*)d_in[3];
    const float* weight   = (const float*)d_in[4];
    const float* attn_src = (const float*)d_in[5];
    const float* attn_dst = (const float*)d_in[6];
    const float* bias     = (const float*)d_in[7];
    float* out = (float*)d_out;

    k01_prep<<<384, 256>>>(adj, x, weight, bias, attn_src, attn_dst, beta, prior);
    k2_attn<<<dim3(N_/64, H_, B_), 256>>>(out);
}